// round 11
// baseline (speedup 1.0000x reference)
#include <cuda_runtime.h>
#include <cuda_fp16.h>
#include <stdint.h>

// Problem constants
#define BATCH   32768
#define NBOOKS  16
#define KCODES  256
#define DDIM    64
#define DECAY_F   0.99f
#define OMDECAY_F 0.010000000000000009f
#define EPS_F     1e-5f

// Output packing (tuple concatenated, f32):
//   codes [B,16] | recon [B,1024] | new_codebooks [16,256,64] | new_count [16,256] | new_weight [16,256,64]
#define OFF_CODES 0LL
#define OFF_RECON (32768LL * 16)
#define OFF_CB    (OFF_RECON + 32768LL * 1024)
#define OFF_CNT   (OFF_CB + 16LL * 256 * 64)
#define OFF_W     (OFF_CNT + 16LL * 256)

// Codebook pre-scale 2^6 (exact; undone by *2^-6) keeps fp16 parts normal.
#define CSCALE   64.0f
#define CUNSCALE 0.015625f
#define MAXCAND  12

// Scratch (device globals: no cudaMalloc allowed)
__device__ float g_counts[NBOOKS * KCODES];
__device__ float g_dw[NBOOKS * KCODES * DDIM];
__device__ uint2 g_bfH[NBOOKS * 128 * 32];   // fp16-high B fragments (k16n8)
__device__ float g_cc[NBOOKS * KCODES];      // ||c_k||^2
__device__ float g_bmax[NBOOKS];             // max_k ||c_k||

// ---------------- assign smem layout (byte offsets), 64-row tile ----------------
#define XP_OFF    0          // float[64][68]  = 17408
#define AH_OFF    17408      // uint4[16][32]  = 8192
#define CC_OFF    25600      // float[256]     = 1024
#define AS_OFF    26624      // float[64]      = 256
#define CANDV_OFF 26880      // float[64*4]    = 1024
#define MINR_OFF  27904      // float[64]      = 256
#define BS_OFF    28160      // float[64]      = 256
#define CNT_OFF   28416      // int[64]        = 256
#define LIST_OFF  28672      // int[64*12]     = 3072
#define CODES_OFF 31744      // int[64]        = 256
#define SM_BYTES  32000

// fp16 split-high: h = rn(v)
__device__ __forceinline__ __half hi_h(float v) { return __float2half_rn(v); }
__device__ __forceinline__ uint32_t pack2(__half lo, __half hi) {
    __half2 p = __halves2half2(lo, hi);
    return *(uint32_t*)&p;
}
// D += A*B, m16n8k16 fp16 -> f32 (arch-portable HMMA)
__device__ __forceinline__ void mma_f16(float* d, const uint32_t* a, uint32_t b0, uint32_t b1) {
    asm volatile("mma.sync.aligned.m16n8k16.row.col.f32.f16.f16.f32 "
        "{%0,%1,%2,%3}, {%4,%5,%6,%7}, {%8,%9}, {%0,%1,%2,%3};"
        : "+f"(d[0]), "+f"(d[1]), "+f"(d[2]), "+f"(d[3])
        : "r"(a[0]), "r"(a[1]), "r"(a[2]), "r"(a[3]), "r"(b0), "r"(b1));
}
// Emulate reference fp32 elementwise: r = fl( fl(A - fl(2*dot)) + cc )
__device__ __forceinline__ float rdist(float A, float dot, float ccv) {
    return __fadd_rn(__fsub_rn(A, __fmul_rn(2.0f, dot)), ccv);
}

// ---- prep: per book, build B-high fragments + cc + bmax, zero counts/dw ----
__global__ void prep_kernel(const float* __restrict__ cbk)
{
    __shared__ float red[8];
    const int n = blockIdx.x;
    const int tid = threadIdx.x;
    const int wid = tid >> 5;
    const int lid = tid & 31;
    const int g = lid >> 2, q = lid & 3;

    g_counts[n * 256 + tid] = 0.0f;
    float4 z4 = make_float4(0.f, 0.f, 0.f, 0.f);
    #pragma unroll
    for (int i = 0; i < 16; i++)
        *(float4*)(g_dw + (size_t)n * 16384 + (i * 256 + tid) * 4) = z4;

    // B-high fragments: f = nt_global*4 + ks, 128 frags, 16 per warp
    #pragma unroll
    for (int it = 0; it < 16; it++) {
        int f = wid * 16 + it;
        int ntg = f >> 2, ks = f & 3;
        int code = ntg * 8 + g;
        int k0 = ks * 16 + 2 * q;
        const float* cr = cbk + ((size_t)(n * 256 + code)) * 64;
        float2 u0 = *(const float2*)(cr + k0);
        float2 u1 = *(const float2*)(cr + k0 + 8);
        g_bfH[((size_t)n * 128 + f) * 32 + lid] = make_uint2(
            pack2(hi_h(u0.x * CSCALE), hi_h(u0.y * CSCALE)),
            pack2(hi_h(u1.x * CSCALE), hi_h(u1.y * CSCALE)));
    }
    // cc (per-lane fmaf + butterfly, same order as passing rounds)
    float mymax = 0.0f;
    #pragma unroll
    for (int it = 0; it < 32; it++) {
        int k = wid * 32 + it;
        float2 cv = *(const float2*)(cbk + ((size_t)(n * 256 + k)) * 64 + 2 * lid);
        float p = fmaf(cv.x, cv.x, cv.y * cv.y);
        #pragma unroll
        for (int off = 16; off > 0; off >>= 1)
            p += __shfl_xor_sync(0xffffffffu, p, off);
        if (lid == 0) g_cc[n * 256 + k] = p;
        if (p > mymax) mymax = p;
    }
    if (lid == 0) red[wid] = mymax;
    __syncthreads();
    if (tid == 0) {
        float m = red[0];
        #pragma unroll
        for (int i = 1; i < 8; i++) m = fmaxf(m, red[i]);
        g_bmax[n] = sqrtf(m);
    }
}

// ---- assign: CTA = 64 rows x book, 256 threads, 2 CTAs/SM ----
__global__ void __launch_bounds__(256, 2)
assign_kernel(const float* __restrict__ x, const float* __restrict__ cbk,
              float* codes_out)
{
    extern __shared__ char sm[];
    float* Xp = (float*)(sm + XP_OFF);
    float* cc = (float*)(sm + CC_OFF);
    float* As = (float*)(sm + AS_OFF);
    float* cand_v = (float*)(sm + CANDV_OFF);
    float* min_row = (float*)(sm + MINR_OFF);
    float* Bs = (float*)(sm + BS_OFF);
    int*   cnt_sm = (int*)(sm + CNT_OFF);
    int*   list_sm = (int*)(sm + LIST_OFF);
    int*   codes_sm = (int*)(sm + CODES_OFF);

    const int tid = threadIdx.x;
    const int wid = tid >> 5;
    const int lid = tid & 31;
    const int g = lid >> 2;
    const int q = lid & 3;
    const int n = blockIdx.y;
    const int row0 = blockIdx.x * 64;
    const float bmax = g_bmax[n];

    // ---- stage x tile (coalesced) ----
    for (int t = tid; t < 1024; t += 256) {
        int r = t >> 4, c4 = t & 15;
        float4 v = *(const float4*)(x + (size_t)(row0 + r) * 1024 + n * 64 + c4 * 4);
        *(float4*)(Xp + r * 68 + c4 * 4) = v;
    }
    __syncthreads();

    // ---- ||x||^2 in the reference's exact fp32 order (bit-critical) ----
    if (tid < 64) {
        const float* xp = Xp + tid * 68;
        float a = 0.0f;
        #pragma unroll
        for (int d = 0; d < 64; d++)
            a = __fadd_rn(a, __fmul_rn(xp[d], xp[d]));
        As[tid] = a;
        cnt_sm[tid] = 0;
    }
    cc[tid] = g_cc[n * 256 + tid];
    // ---- A-high fragments: 16 frags = mt*4+ks, 2 per warp ----
    #pragma unroll
    for (int i = 0; i < 2; i++) {
        int f = wid * 2 + i;
        int mt = f >> 2, ks = f & 3;
        int r1 = mt * 16 + g;
        int c0 = ks * 16 + 2 * q;
        float2 p0 = *(const float2*)(Xp + r1 * 68 + c0);
        float2 p1 = *(const float2*)(Xp + (r1 + 8) * 68 + c0);
        float2 p2 = *(const float2*)(Xp + r1 * 68 + c0 + 8);
        float2 p3 = *(const float2*)(Xp + (r1 + 8) * 68 + c0 + 8);
        uint4 H = make_uint4(pack2(hi_h(p0.x), hi_h(p0.y)), pack2(hi_h(p1.x), hi_h(p1.y)),
                             pack2(hi_h(p2.x), hi_h(p2.y)), pack2(hi_h(p3.x), hi_h(p3.y)));
        *(uint4*)(sm + AH_OFF + (f * 32 + lid) * 16) = H;
    }
    __syncthreads();

    // ---- mainloop (hh product only): warp (mw, nw): rows mw*32..+31, cols nw*64..+63 ----
    const int mw = wid & 1;
    const int nw = wid >> 1;            // 0..3
    float acc[2][8][4];
    #pragma unroll
    for (int mt = 0; mt < 2; mt++)
        #pragma unroll
        for (int nt = 0; nt < 8; nt++)
            #pragma unroll
            for (int e = 0; e < 4; e++) acc[mt][nt][e] = 0.0f;

    const uint2* bH = g_bfH + ((size_t)n * 128) * 32 + lid;

    #pragma unroll
    for (int ks = 0; ks < 4; ks++) {
        uint4 ah0 = *(const uint4*)(sm + AH_OFF + (((2 * mw) * 4 + ks) * 32 + lid) * 16);
        uint4 ah1 = *(const uint4*)(sm + AH_OFF + (((2 * mw + 1) * 4 + ks) * 32 + lid) * 16);
        #pragma unroll
        for (int nt = 0; nt < 8; nt++) {
            int f = (8 * nw + nt) * 4 + ks;
            uint2 bh = __ldg(bH + f * 32);
            mma_f16(acc[0][nt], (const uint32_t*)&ah0, bh.x, bh.y);
            mma_f16(acc[1][nt], (const uint32_t*)&ah1, bh.x, bh.y);
        }
    }

    // ---- pass A: cheap scores (overwrite acc), per-(row, nw) min ----
    float ccv[16];
    #pragma unroll
    for (int nt = 0; nt < 8; nt++) {
        float2 cp = *(const float2*)(cc + 64 * nw + 8 * nt + 2 * q);
        ccv[2 * nt] = cp.x; ccv[2 * nt + 1] = cp.y;
    }
    #pragma unroll
    for (int mt = 0; mt < 2; mt++) {
        #pragma unroll
        for (int rr = 0; rr < 2; rr++) {
            int lrow = mw * 32 + mt * 16 + rr * 8 + g;
            float A = As[lrow];
            float v = 3.4e38f;
            #pragma unroll
            for (int nt = 0; nt < 8; nt++) {
                #pragma unroll
                for (int e = 0; e < 2; e++) {
                    float s = rdist(A, acc[mt][nt][rr * 2 + e] * CUNSCALE, ccv[2 * nt + e]);
                    acc[mt][nt][rr * 2 + e] = s;     // keep for pass B
                    v = fminf(v, s);
                }
            }
            #pragma unroll
            for (int off = 1; off <= 2; off <<= 1)
                v = fminf(v, __shfl_xor_sync(0xffffffffu, v, off));
            if (q == 0) cand_v[lrow * 4 + nw] = v;
        }
    }
    __syncthreads();
    // combine 4 blocks; per-row threshold B = 2^-8*||x||*bmax + slack
    if (tid < 64) {
        float v = fminf(fminf(cand_v[tid * 4], cand_v[tid * 4 + 1]),
                        fminf(cand_v[tid * 4 + 2], cand_v[tid * 4 + 3]));
        min_row[tid] = v;
        Bs[tid] = 0.00390625f * sqrtf(As[tid]) * bmax + 4e-4f;
    }
    __syncthreads();

    // ---- pass B: collect candidates (s <= min + B) ----
    #pragma unroll
    for (int mt = 0; mt < 2; mt++) {
        #pragma unroll
        for (int rr = 0; rr < 2; rr++) {
            int lrow = mw * 32 + mt * 16 + rr * 8 + g;
            float thr = min_row[lrow] + Bs[lrow];
            #pragma unroll
            for (int nt = 0; nt < 8; nt++) {
                #pragma unroll
                for (int e = 0; e < 2; e++) {
                    if (acc[mt][nt][rr * 2 + e] <= thr) {
                        int k = 64 * nw + 8 * nt + 2 * q + e;
                        int pos = atomicAdd(&cnt_sm[lrow], 1);
                        if (pos < MAXCAND) list_sm[lrow * MAXCAND + pos] = k;
                    }
                }
            }
        }
    }
    __syncthreads();

    // ---- pass C: exact refine per row (scalar fp32, reference rounding) ----
    if (tid < 64) {
        const int row = tid;
        const int cntr = cnt_sm[row];
        const float A = As[row];
        const float* xr = Xp + row * 68;
        int bi;
        if (cntr == 1) {
            bi = list_sm[row * MAXCAND];
        } else if (cntr <= MAXCAND) {
            float best = 3.4e38f; bi = 256;
            for (int i = 0; i < cntr; i++) {
                int k = list_sm[row * MAXCAND + i];
                const float* cr = cbk + ((size_t)(n * 256 + k)) * 64;
                float dot = 0.0f;
                #pragma unroll
                for (int d = 0; d < 64; d++) dot = fmaf(xr[d], cr[d], dot);
                float r = rdist(A, dot, cc[k]);
                if (r < best || (r == best && k < bi)) { best = r; bi = k; }
            }
        } else {
            // overflow (effectively never): exact full scan, ascending k
            float best = 3.4e38f; bi = 0;
            for (int k = 0; k < 256; k++) {
                const float* cr = cbk + ((size_t)(n * 256 + k)) * 64;
                float dot = 0.0f;
                for (int d = 0; d < 64; d++) dot = fmaf(xr[d], cr[d], dot);
                float r = rdist(A, dot, cc[k]);
                if (r < best) { best = r; bi = k; }
            }
        }
        codes_sm[row] = bi;
        codes_out[(size_t)(row0 + row) * NBOOKS + n] = (float)bi;
        atomicAdd(&g_counts[n * KCODES + bi], 1.0f);
    }
    __syncthreads();

    // ---- dw scatter: warp per 8 rows, red.global.add.v4.f32 (16 active lanes) ----
    // 4x fewer REDG lane-ops than scalar: this was the exposed bottleneck.
    if (lid < 16) {
        const int rb = wid * 8;
        #pragma unroll
        for (int i = 0; i < 8; i++) {
            int r = rb + i;
            int bi = codes_sm[r];
            float4 v = *(const float4*)(Xp + r * 68 + 4 * lid);
            float* dst = &g_dw[((size_t)(n * KCODES + bi)) * 64 + 4 * lid];
            asm volatile("red.global.add.v4.f32 [%0], {%1, %2, %3, %4};"
                         :: "l"(dst), "f"(v.x), "f"(v.y), "f"(v.z), "f"(v.w) : "memory");
        }
    }
}

// EMA update + write count/weight/codebook outputs.
__global__ void ema_kernel(const float* __restrict__ ec, const float* __restrict__ ew,
                           float* out)
{
    int i = blockIdx.x * blockDim.x + threadIdx.x;
    if (i >= NBOOKS * KCODES * 16) return;
    int d4 = i & 15;
    int nk = i >> 4;
    float nc = DECAY_F * ec[nk] + OMDECAY_F * g_counts[nk];
    float4 w  = *(const float4*)(ew + (size_t)nk * 64 + d4 * 4);
    float4 dv = *(const float4*)(g_dw + (size_t)nk * 64 + d4 * 4);
    float4 nw;
    nw.x = DECAY_F * w.x + OMDECAY_F * dv.x;
    nw.y = DECAY_F * w.y + OMDECAY_F * dv.y;
    nw.z = DECAY_F * w.z + OMDECAY_F * dv.z;
    nw.w = DECAY_F * w.w + OMDECAY_F * dv.w;
    float den = nc + EPS_F;
    float4 cbv;
    cbv.x = nw.x / den; cbv.y = nw.y / den; cbv.z = nw.z / den; cbv.w = nw.w / den;
    *(float4*)(out + OFF_W  + (size_t)nk * 64 + d4 * 4) = nw;
    *(float4*)(out + OFF_CB + (size_t)nk * 64 + d4 * 4) = cbv;
    if (d4 == 0) out[OFF_CNT + nk] = nc;
}

// recon gather, 4 independent chains per thread for ILP
#define RECON_Q (BATCH * NBOOKS * 16 / 4)
__global__ void recon_kernel(float* out)
{
    int idx = blockIdx.x * blockDim.x + threadIdx.x;
    #pragma unroll
    for (int h = 0; h < 4; h++) {
        int i = idx + h * RECON_Q;
        int d4 = i & 15;
        int bn = i >> 4;
        int n  = bn & 15;
        int b  = bn >> 4;
        int k  = (int)out[OFF_CODES + bn];
        float4 v = *(const float4*)(out + OFF_CB + ((size_t)(n * KCODES + k)) * 64 + d4 * 4);
        *(float4*)(out + OFF_RECON + (size_t)b * 1024 + n * 64 + d4 * 4) = v;
    }
}

extern "C" void kernel_launch(void* const* d_in, const int* in_sizes, int n_in,
                              void* d_out, int out_size)
{
    const float* x   = (const float*)d_in[0];
    const float* cbk = (const float*)d_in[1];
    const float* ec  = (const float*)d_in[2];
    const float* ew  = (const float*)d_in[3];
    float* out = (float*)d_out;

    prep_kernel<<<NBOOKS, 256>>>(cbk);
    dim3 grid(BATCH / 64, NBOOKS);
    assign_kernel<<<grid, 256, SM_BYTES>>>(x, cbk, out + OFF_CODES);
    ema_kernel<<<(NBOOKS * KCODES * 16) / 256, 256>>>(ec, ew, out);
    recon_kernel<<<RECON_Q / 256, 256>>>(out);
}

// round 13
// speedup vs baseline: 1.0825x; 1.0825x over previous
#include <cuda_runtime.h>
#include <cuda_fp16.h>
#include <stdint.h>

// Problem constants
#define BATCH   32768
#define NBOOKS  16
#define KCODES  256
#define DDIM    64
#define DECAY_F   0.99f
#define OMDECAY_F 0.010000000000000009f
#define EPS_F     1e-5f

// Output packing (tuple concatenated, f32):
//   codes [B,16] | recon [B,1024] | new_codebooks [16,256,64] | new_count [16,256] | new_weight [16,256,64]
#define OFF_CODES 0LL
#define OFF_RECON (32768LL * 16)
#define OFF_CB    (OFF_RECON + 32768LL * 1024)
#define OFF_CNT   (OFF_CB + 16LL * 256 * 64)
#define OFF_W     (OFF_CNT + 16LL * 256)

// Codebook pre-scale 2^6 (exact; undone by *2^-6) keeps fp16 parts normal.
#define CSCALE   64.0f
#define CUNSCALE 0.015625f
#define MAXCAND  12

// Scratch (device globals: no cudaMalloc allowed)
__device__ float g_counts[NBOOKS * KCODES];
__device__ float g_dw[NBOOKS * KCODES * DDIM];
__device__ uint2 g_bfH[NBOOKS * 128 * 32];   // fp16-high B fragments (k16n8)
__device__ float g_cc[NBOOKS * KCODES];      // ||c_k||^2

// ---------------- assign smem layout (byte offsets), 64-row tile ----------------
#define XP_OFF    0          // float[64][68]  = 17408
#define AH_OFF    17408      // uint4[16][32]  = 8192
#define BSM_OFF   25600      // uint2[128][32] = 32768  (B-high fragments, whole book)
#define CC_OFF    58368      // float[256]     = 1024
#define AS_OFF    59392      // float[64]      = 256
#define CANDV_OFF 59648      // float[64*4]    = 1024
#define MINR_OFF  60672      // float[64]      = 256
#define BS_OFF    60928      // float[64]      = 256
#define CNT_OFF   61184      // int[64]        = 256
#define LIST_OFF  61440      // int[64*12]     = 3072
#define CODES_OFF 64512      // int[64]        = 256
#define WMAX_OFF  64768      // float[8]       = 32
#define SM_BYTES  64800

// fp16 split-high: h = rn(v)
__device__ __forceinline__ __half hi_h(float v) { return __float2half_rn(v); }
__device__ __forceinline__ uint32_t pack2(__half lo, __half hi) {
    __half2 p = __halves2half2(lo, hi);
    return *(uint32_t*)&p;
}
// D += A*B, m16n8k16 fp16 -> f32 (arch-portable HMMA)
__device__ __forceinline__ void mma_f16(float* d, const uint32_t* a, uint32_t b0, uint32_t b1) {
    asm volatile("mma.sync.aligned.m16n8k16.row.col.f32.f16.f16.f32 "
        "{%0,%1,%2,%3}, {%4,%5,%6,%7}, {%8,%9}, {%0,%1,%2,%3};"
        : "+f"(d[0]), "+f"(d[1]), "+f"(d[2]), "+f"(d[3])
        : "r"(a[0]), "r"(a[1]), "r"(a[2]), "r"(a[3]), "r"(b0), "r"(b1));
}
// Emulate reference fp32 elementwise: r = fl( fl(A - fl(2*dot)) + cc )
__device__ __forceinline__ float rdist(float A, float dot, float ccv) {
    return __fadd_rn(__fsub_rn(A, __fmul_rn(2.0f, dot)), ccv);
}

// ---- prep: per book, build B-high fragments + cc, zero counts/dw ----
__global__ void prep_kernel(const float* __restrict__ cbk)
{
    const int n = blockIdx.x;
    const int tid = threadIdx.x;
    const int wid = tid >> 5;
    const int lid = tid & 31;
    const int g = lid >> 2, q = lid & 3;

    g_counts[n * 256 + tid] = 0.0f;
    float4 z4 = make_float4(0.f, 0.f, 0.f, 0.f);
    #pragma unroll
    for (int i = 0; i < 16; i++)
        *(float4*)(g_dw + (size_t)n * 16384 + (i * 256 + tid) * 4) = z4;

    // B-high fragments: f = nt_global*4 + ks, 128 frags, 16 per warp
    #pragma unroll
    for (int it = 0; it < 16; it++) {
        int f = wid * 16 + it;
        int ntg = f >> 2, ks = f & 3;
        int code = ntg * 8 + g;
        int k0 = ks * 16 + 2 * q;
        const float* cr = cbk + ((size_t)(n * 256 + code)) * 64;
        float2 u0 = *(const float2*)(cr + k0);
        float2 u1 = *(const float2*)(cr + k0 + 8);
        g_bfH[((size_t)n * 128 + f) * 32 + lid] = make_uint2(
            pack2(hi_h(u0.x * CSCALE), hi_h(u0.y * CSCALE)),
            pack2(hi_h(u1.x * CSCALE), hi_h(u1.y * CSCALE)));
    }
    // cc (per-lane fmaf + butterfly, same order as passing rounds)
    #pragma unroll
    for (int it = 0; it < 32; it++) {
        int k = wid * 32 + it;
        float2 cv = *(const float2*)(cbk + ((size_t)(n * 256 + k)) * 64 + 2 * lid);
        float p = fmaf(cv.x, cv.x, cv.y * cv.y);
        #pragma unroll
        for (int off = 16; off > 0; off >>= 1)
            p += __shfl_xor_sync(0xffffffffu, p, off);
        if (lid == 0) g_cc[n * 256 + k] = p;
    }
}

// ---- assign: CTA = 64 rows x book, 256 threads, 2 CTAs/SM ----
__global__ void __launch_bounds__(256, 2)
assign_kernel(const float* __restrict__ x, const float* __restrict__ cbk,
              float* codes_out)
{
    extern __shared__ char sm[];
    float* Xp = (float*)(sm + XP_OFF);
    float* cc = (float*)(sm + CC_OFF);
    float* As = (float*)(sm + AS_OFF);
    float* cand_v = (float*)(sm + CANDV_OFF);
    float* min_row = (float*)(sm + MINR_OFF);
    float* Bs = (float*)(sm + BS_OFF);
    int*   cnt_sm = (int*)(sm + CNT_OFF);
    int*   list_sm = (int*)(sm + LIST_OFF);
    int*   codes_sm = (int*)(sm + CODES_OFF);
    float* wmax = (float*)(sm + WMAX_OFF);

    const int tid = threadIdx.x;
    const int wid = tid >> 5;
    const int lid = tid & 31;
    const int g = lid >> 2;
    const int q = lid & 3;
    const int n = blockIdx.y;
    const int row0 = blockIdx.x * 64;

    // ---- phase 0: issue ALL gmem loads back-to-back (deep MLP, one latency hit) ----
    // x tile: 4 float4 per thread
    float4 xs[4];
    {
        int r = tid >> 2, c4g = (tid & 3) * 4;   // 4 consecutive float4 per thread
        const float4* src = (const float4*)(x + (size_t)(row0 + r) * 1024 + n * 64 + c4g * 4);
        #pragma unroll
        for (int j = 0; j < 4; j++) xs[j] = src[j];
        // B fragments for the whole book: 8 uint4 per thread
        const uint4* bsrc = (const uint4*)(g_bfH + (size_t)n * 4096);
        uint4 bs[8];
        #pragma unroll
        for (int j = 0; j < 8; j++) bs[j] = __ldg(bsrc + tid + j * 256);
        float ccval = g_cc[n * 256 + tid];
        // commit to smem
        #pragma unroll
        for (int j = 0; j < 4; j++)
            *(float4*)(Xp + r * 68 + (c4g + j) * 4) = xs[j];
        #pragma unroll
        for (int j = 0; j < 8; j++)
            *(uint4*)(sm + BSM_OFF + (tid + j * 256) * 16) = bs[j];
        cc[tid] = ccval;
        // warp max of cc (for candidate threshold); butterfly makes it warp-uniform
        float m = ccval;
        #pragma unroll
        for (int off = 16; off > 0; off >>= 1)
            m = fmaxf(m, __shfl_xor_sync(0xffffffffu, m, off));
        if (lid == 0) wmax[wid] = m;
    }
    __syncthreads();

    // ---- ||x||^2 in the reference's exact fp32 order (bit-critical) ----
    if (tid < 64) {
        const float* xp = Xp + tid * 68;
        float a = 0.0f;
        #pragma unroll
        for (int d = 0; d < 64; d++)
            a = __fadd_rn(a, __fmul_rn(xp[d], xp[d]));
        As[tid] = a;
        cnt_sm[tid] = 0;
    }
    // ---- A-high fragments: 16 frags = mt*4+ks, 2 per warp ----
    #pragma unroll
    for (int i = 0; i < 2; i++) {
        int f = wid * 2 + i;
        int mt = f >> 2, ks = f & 3;
        int r1 = mt * 16 + g;
        int c0 = ks * 16 + 2 * q;
        float2 p0 = *(const float2*)(Xp + r1 * 68 + c0);
        float2 p1 = *(const float2*)(Xp + (r1 + 8) * 68 + c0);
        float2 p2 = *(const float2*)(Xp + r1 * 68 + c0 + 8);
        float2 p3 = *(const float2*)(Xp + (r1 + 8) * 68 + c0 + 8);
        uint4 H = make_uint4(pack2(hi_h(p0.x), hi_h(p0.y)), pack2(hi_h(p1.x), hi_h(p1.y)),
                             pack2(hi_h(p2.x), hi_h(p2.y)), pack2(hi_h(p3.x), hi_h(p3.y)));
        *(uint4*)(sm + AH_OFF + (f * 32 + lid) * 16) = H;
    }
    __syncthreads();

    // ---- mainloop (hh product, all operands in smem) ----
    const int mw = wid & 1;
    const int nw = wid >> 1;            // 0..3
    float acc[2][8][4];
    #pragma unroll
    for (int mt = 0; mt < 2; mt++)
        #pragma unroll
        for (int nt = 0; nt < 8; nt++)
            #pragma unroll
            for (int e = 0; e < 4; e++) acc[mt][nt][e] = 0.0f;

    #pragma unroll
    for (int ks = 0; ks < 4; ks++) {
        uint4 ah0 = *(const uint4*)(sm + AH_OFF + (((2 * mw) * 4 + ks) * 32 + lid) * 16);
        uint4 ah1 = *(const uint4*)(sm + AH_OFF + (((2 * mw + 1) * 4 + ks) * 32 + lid) * 16);
        #pragma unroll
        for (int nt = 0; nt < 8; nt++) {
            int f = (8 * nw + nt) * 4 + ks;
            uint2 bh = *(const uint2*)(sm + BSM_OFF + (f * 32 + lid) * 8);
            mma_f16(acc[0][nt], (const uint32_t*)&ah0, bh.x, bh.y);
            mma_f16(acc[1][nt], (const uint32_t*)&ah1, bh.x, bh.y);
        }
    }

    // ---- pass A: cheap scores (overwrite acc), per-(row, nw) min ----
    float ccv[16];
    #pragma unroll
    for (int nt = 0; nt < 8; nt++) {
        float2 cp = *(const float2*)(cc + 64 * nw + 8 * nt + 2 * q);
        ccv[2 * nt] = cp.x; ccv[2 * nt + 1] = cp.y;
    }
    #pragma unroll
    for (int mt = 0; mt < 2; mt++) {
        #pragma unroll
        for (int rr = 0; rr < 2; rr++) {
            int lrow = mw * 32 + mt * 16 + rr * 8 + g;
            float A = As[lrow];
            float v = 3.4e38f;
            #pragma unroll
            for (int nt = 0; nt < 8; nt++) {
                #pragma unroll
                for (int e = 0; e < 2; e++) {
                    float s = rdist(A, acc[mt][nt][rr * 2 + e] * CUNSCALE, ccv[2 * nt + e]);
                    acc[mt][nt][rr * 2 + e] = s;     // keep for pass B
                    v = fminf(v, s);
                }
            }
            #pragma unroll
            for (int off = 1; off <= 2; off <<= 1)
                v = fminf(v, __shfl_xor_sync(0xffffffffu, v, off));
            if (q == 0) cand_v[lrow * 4 + nw] = v;
        }
    }
    __syncthreads();
    // combine 4 blocks; per-row threshold B = 2^-8*||x||*bmax + slack
    if (tid < 64) {
        float v = fminf(fminf(cand_v[tid * 4], cand_v[tid * 4 + 1]),
                        fminf(cand_v[tid * 4 + 2], cand_v[tid * 4 + 3]));
        min_row[tid] = v;
        float m = wmax[0];
        #pragma unroll
        for (int i = 1; i < 8; i++) m = fmaxf(m, wmax[i]);
        Bs[tid] = 0.00390625f * sqrtf(As[tid]) * sqrtf(m) + 4e-4f;
    }
    __syncthreads();

    // ---- pass B: collect candidates (s <= min + B) ----
    #pragma unroll
    for (int mt = 0; mt < 2; mt++) {
        #pragma unroll
        for (int rr = 0; rr < 2; rr++) {
            int lrow = mw * 32 + mt * 16 + rr * 8 + g;
            float thr = min_row[lrow] + Bs[lrow];
            #pragma unroll
            for (int nt = 0; nt < 8; nt++) {
                #pragma unroll
                for (int e = 0; e < 2; e++) {
                    if (acc[mt][nt][rr * 2 + e] <= thr) {
                        int k = 64 * nw + 8 * nt + 2 * q + e;
                        int pos = atomicAdd(&cnt_sm[lrow], 1);
                        if (pos < MAXCAND) list_sm[lrow * MAXCAND + pos] = k;
                    }
                }
            }
        }
    }
    __syncthreads();

    // ---- pass C: exact refine per row (scalar fp32, reference rounding) ----
    if (tid < 64) {
        const int row = tid;
        const int cntr = cnt_sm[row];
        const float A = As[row];
        const float* xr = Xp + row * 68;
        int bi;
        if (cntr == 1) {
            bi = list_sm[row * MAXCAND];
        } else if (cntr <= MAXCAND) {
            float best = 3.4e38f; bi = 256;
            for (int i = 0; i < cntr; i++) {
                int k = list_sm[row * MAXCAND + i];
                const float* cr = cbk + ((size_t)(n * 256 + k)) * 64;
                float dot = 0.0f;
                #pragma unroll
                for (int d = 0; d < 64; d++) dot = fmaf(xr[d], cr[d], dot);
                float r = rdist(A, dot, cc[k]);
                if (r < best || (r == best && k < bi)) { best = r; bi = k; }
            }
        } else {
            // overflow (effectively never): exact full scan, ascending k
            float best = 3.4e38f; bi = 0;
            for (int k = 0; k < 256; k++) {
                const float* cr = cbk + ((size_t)(n * 256 + k)) * 64;
                float dot = 0.0f;
                for (int d = 0; d < 64; d++) dot = fmaf(xr[d], cr[d], dot);
                float r = rdist(A, dot, cc[k]);
                if (r < best) { best = r; bi = k; }
            }
        }
        codes_sm[row] = bi;
        codes_out[(size_t)(row0 + row) * NBOOKS + n] = (float)bi;
        atomicAdd(&g_counts[n * KCODES + bi], 1.0f);
    }
    __syncthreads();

    // ---- dw scatter: warp per 8 rows, red.global.add.v4.f32 (16 active lanes) ----
    if (lid < 16) {
        const int rb = wid * 8;
        #pragma unroll
        for (int i = 0; i < 8; i++) {
            int r = rb + i;
            int bi = codes_sm[r];
            float4 v = *(const float4*)(Xp + r * 68 + 4 * lid);
            float* dst = &g_dw[((size_t)(n * KCODES + bi)) * 64 + 4 * lid];
            asm volatile("red.global.add.v4.f32 [%0], {%1, %2, %3, %4};"
                         :: "l"(dst), "f"(v.x), "f"(v.y), "f"(v.z), "f"(v.w) : "memory");
        }
    }
}

// EMA update + write count/weight/codebook outputs.
__global__ void ema_kernel(const float* __restrict__ ec, const float* __restrict__ ew,
                           float* out)
{
    int i = blockIdx.x * blockDim.x + threadIdx.x;
    if (i >= NBOOKS * KCODES * 16) return;
    int d4 = i & 15;
    int nk = i >> 4;
    float nc = DECAY_F * ec[nk] + OMDECAY_F * g_counts[nk];
    float4 w  = *(const float4*)(ew + (size_t)nk * 64 + d4 * 4);
    float4 dv = *(const float4*)(g_dw + (size_t)nk * 64 + d4 * 4);
    float4 nw;
    nw.x = DECAY_F * w.x + OMDECAY_F * dv.x;
    nw.y = DECAY_F * w.y + OMDECAY_F * dv.y;
    nw.z = DECAY_F * w.z + OMDECAY_F * dv.z;
    nw.w = DECAY_F * w.w + OMDECAY_F * dv.w;
    float den = nc + EPS_F;
    float4 cbv;
    cbv.x = nw.x / den; cbv.y = nw.y / den; cbv.z = nw.z / den; cbv.w = nw.w / den;
    *(float4*)(out + OFF_W  + (size_t)nk * 64 + d4 * 4) = nw;
    *(float4*)(out + OFF_CB + (size_t)nk * 64 + d4 * 4) = cbv;
    if (d4 == 0) out[OFF_CNT + nk] = nc;
}

// recon gather, 8 independent chains per thread for ILP
#define RECON_Q (BATCH * NBOOKS * 16 / 8)
__global__ void recon_kernel(float* out)
{
    int idx = blockIdx.x * blockDim.x + threadIdx.x;
    #pragma unroll
    for (int h = 0; h < 8; h++) {
        int i = idx + h * RECON_Q;
        int d4 = i & 15;
        int bn = i >> 4;
        int n  = bn & 15;
        int b  = bn >> 4;
        int k  = (int)out[OFF_CODES + bn];
        float4 v = *(const float4*)(out + OFF_CB + ((size_t)(n * KCODES + k)) * 64 + d4 * 4);
        *(float4*)(out + OFF_RECON + (size_t)b * 1024 + n * 64 + d4 * 4) = v;
    }
}

extern "C" void kernel_launch(void* const* d_in, const int* in_sizes, int n_in,
                              void* d_out, int out_size)
{
    const float* x   = (const float*)d_in[0];
    const float* cbk = (const float*)d_in[1];
    const float* ec  = (const float*)d_in[2];
    const float* ew  = (const float*)d_in[3];
    float* out = (float*)d_out;

    cudaFuncSetAttribute(assign_kernel,
                         cudaFuncAttributeMaxDynamicSharedMemorySize, SM_BYTES);

    prep_kernel<<<NBOOKS, 256>>>(cbk);
    dim3 grid(BATCH / 64, NBOOKS);
    assign_kernel<<<grid, 256, SM_BYTES>>>(x, cbk, out + OFF_CODES);
    ema_kernel<<<(NBOOKS * KCODES * 16) / 256, 256>>>(ec, ew, out);
    recon_kernel<<<RECON_Q / 256, 256>>>(out);
}